// round 5
// baseline (speedup 1.0000x reference)
#include <cuda_runtime.h>
#include <cuda_bf16.h>

#define NMAX   100000
#define EMAX   640000
#define LATDIM 128
#define VEC    32          // float4 per row
#define SCAN_B 1024
#define RPW    4           // rows per warp in spmm

// ---- scratch (__device__ globals; allocation-free rule) --------------------
__device__ float  g_bufA[(size_t)NMAX * LATDIM];
__device__ float  g_bufB[(size_t)NMAX * LATDIM];
__device__ float2 g_stats[NMAX];     // {mu, inv} per node
__device__ int    g_cnt[NMAX];
__device__ int    g_rowstart[NMAX];
__device__ int    g_bsum[SCAN_B];
__device__ int    g_bpref[SCAN_B];
__device__ int    g_rank[EMAX];
__device__ uint2  g_edges[EMAX];     // row-sorted {col, val bits}

// ---------------------------------------------------------------------------
// prep: warp per node — LN stats {mu, inv}; lane0 also zeroes g_cnt
// ---------------------------------------------------------------------------
__global__ void prep_kernel(const float* __restrict__ in, int n_nodes) {
    int gw   = (blockIdx.x * blockDim.x + threadIdx.x) >> 5;
    int lane = threadIdx.x & 31;
    if (gw >= n_nodes) return;

    float4 v = __ldg(reinterpret_cast<const float4*>(in) + (size_t)gw * VEC + lane);

    float s  = v.x + v.y + v.z + v.w;
    float ss = v.x * v.x + v.y * v.y + v.z * v.z + v.w * v.w;
    #pragma unroll
    for (int o = 16; o > 0; o >>= 1) {
        s  += __shfl_xor_sync(0xFFFFFFFFu, s,  o);
        ss += __shfl_xor_sync(0xFFFFFFFFu, ss, o);
    }
    if (lane == 0) {
        float mu  = s * (1.0f / LATDIM);
        float var = ss * (1.0f / LATDIM) - mu * mu;
        g_stats[gw] = make_float2(mu, rsqrtf(var + 1e-5f));
        g_cnt[gw]   = 0;
    }
}

// ---------------------------------------------------------------------------
// hist: degree count; atomic return value IS the within-row rank
// ---------------------------------------------------------------------------
__global__ void hist_kernel(const int* __restrict__ row, int n_edges) {
    int e      = blockIdx.x * blockDim.x + threadIdx.x;
    int stride = gridDim.x * blockDim.x;
    for (; e < n_edges; e += stride)
        g_rank[e] = atomicAdd(&g_cnt[row[e]], 1);
}

// warp-shuffle block scan (exclusive), emits block total
__global__ void scan1_kernel(int n_nodes) {
    __shared__ int wsum[32];
    int t = threadIdx.x, lane = t & 31, wid = t >> 5;
    int i = blockIdx.x * SCAN_B + t;
    int v = (i < n_nodes) ? g_cnt[i] : 0;

    int x = v;
    #pragma unroll
    for (int o = 1; o < 32; o <<= 1) {
        int y = __shfl_up_sync(0xFFFFFFFFu, x, o);
        if (lane >= o) x += y;
    }
    if (lane == 31) wsum[wid] = x;
    __syncthreads();
    if (wid == 0) {
        int s = wsum[lane];
        #pragma unroll
        for (int o = 1; o < 32; o <<= 1) {
            int y = __shfl_up_sync(0xFFFFFFFFu, s, o);
            if (lane >= o) s += y;
        }
        wsum[lane] = s;
    }
    __syncthreads();
    int incl = x + (wid ? wsum[wid - 1] : 0);
    if (i < n_nodes) g_rowstart[i] = incl - v;
    if (t == SCAN_B - 1) g_bsum[blockIdx.x] = incl;
}

__global__ void scan2_kernel(int n_blocks) {
    __shared__ int wsum[32];
    int t = threadIdx.x, lane = t & 31, wid = t >> 5;
    int v = (t < n_blocks) ? g_bsum[t] : 0;

    int x = v;
    #pragma unroll
    for (int o = 1; o < 32; o <<= 1) {
        int y = __shfl_up_sync(0xFFFFFFFFu, x, o);
        if (lane >= o) x += y;
    }
    if (lane == 31) wsum[wid] = x;
    __syncthreads();
    if (wid == 0) {
        int s = wsum[lane];
        #pragma unroll
        for (int o = 1; o < 32; o <<= 1) {
            int y = __shfl_up_sync(0xFFFFFFFFu, s, o);
            if (lane >= o) s += y;
        }
        wsum[lane] = s;
    }
    __syncthreads();
    int incl = x + (wid ? wsum[wid - 1] : 0);
    g_bpref[t] = incl - v;
}

// atomic-free scatter using precomputed ranks
__global__ void scatter_kernel(const int* __restrict__ row,
                               const int* __restrict__ col,
                               const float* __restrict__ val,
                               int n_edges) {
    int e      = blockIdx.x * blockDim.x + threadIdx.x;
    int stride = gridDim.x * blockDim.x;
    for (; e < n_edges; e += stride) {
        int r    = row[e];
        int base = g_rowstart[r] + g_bpref[r >> 10];
        g_edges[base + g_rank[e]] =
            make_uint2((unsigned)col[e], __float_as_uint(val[e]));
    }
}

// ---------------------------------------------------------------------------
// SpMM: 4 rows per warp, lane owns one float4 of each row.
// Inner loop interleaves the 4 rows' edge streams -> 4 independent gather
// chains in flight. Edge meta via uniform broadcast LDG (no shuffles).
// LAYER 0: x = embeds, LN applied on the fly via g_stats; y = acc
// LAYER 1: y = acc
// LAYER 2: out = acc + y1[r] + x[r]   (x row == y2), streaming hints
// ---------------------------------------------------------------------------
template <int LAYER>
__global__ void __launch_bounds__(256)
spmm_kernel(const float* __restrict__ x,
            float* __restrict__ y,
            const float* __restrict__ y1,
            float* __restrict__ out,
            int n_nodes) {
    int gw = (blockIdx.x * blockDim.x + threadIdx.x) >> 5;
    int r0 = gw * RPW;
    if (r0 >= n_nodes) return;
    int lane = threadIdx.x & 31;

    int base[RPW], deg[RPW];
    #pragma unroll
    for (int j = 0; j < RPW; ++j) {
        int r = r0 + j;
        bool ok = (r < n_nodes);
        base[j] = ok ? (g_rowstart[r] + g_bpref[r >> 10]) : 0;
        deg[j]  = ok ? g_cnt[r] : 0;
    }
    int maxdeg = max(max(deg[0], deg[1]), max(deg[2], deg[3]));

    const float4* x4 = reinterpret_cast<const float4*>(x);
    float4 acc[RPW];
    #pragma unroll
    for (int j = 0; j < RPW; ++j) acc[j] = make_float4(0.f, 0.f, 0.f, 0.f);

    for (int t = 0; t < maxdeg; ++t) {
        #pragma unroll
        for (int j = 0; j < RPW; ++j) {
            if (t < deg[j]) {                       // warp-uniform branch
                uint2 ev = __ldg(&g_edges[base[j] + t]);   // broadcast load
                int   c  = (int)ev.x;
                float v  = __uint_as_float(ev.y);
                float4 xv = __ldg(x4 + (size_t)c * VEC + lane);
                if (LAYER == 0) {
                    float2 st = __ldg(&g_stats[c]);
                    float sc  = v * st.y;            // v * inv
                    float sb  = sc * st.x;           // v * inv * mu
                    acc[j].x = fmaf(sc, xv.x, acc[j].x - sb);
                    acc[j].y = fmaf(sc, xv.y, acc[j].y - sb);
                    acc[j].z = fmaf(sc, xv.z, acc[j].z - sb);
                    acc[j].w = fmaf(sc, xv.w, acc[j].w - sb);
                } else {
                    acc[j].x = fmaf(v, xv.x, acc[j].x);
                    acc[j].y = fmaf(v, xv.y, acc[j].y);
                    acc[j].z = fmaf(v, xv.z, acc[j].z);
                    acc[j].w = fmaf(v, xv.w, acc[j].w);
                }
            }
        }
    }

    #pragma unroll
    for (int j = 0; j < RPW; ++j) {
        int r = r0 + j;
        if (r >= n_nodes) break;
        size_t oi = (size_t)r * VEC + lane;
        if (LAYER < 2) {
            reinterpret_cast<float4*>(y)[oi] = acc[j];  // stays L2-hot
        } else {
            float4 a = __ldcs(reinterpret_cast<const float4*>(y1) + oi); // y1: evict-first
            float4 b = __ldg(x4 + oi);                                   // y2 row: L2-hot
            acc[j].x += a.x + b.x; acc[j].y += a.y + b.y;
            acc[j].z += a.z + b.z; acc[j].w += a.w + b.w;
            __stcs(reinterpret_cast<float4*>(out) + oi, acc[j]);         // streaming
        }
    }
}

// ---------------------------------------------------------------------------
// Launcher
// ---------------------------------------------------------------------------
extern "C" void kernel_launch(void* const* d_in, const int* in_sizes, int n_in,
                              void* d_out, int out_size) {
    const float* embeds  = (const float*)d_in[0];
    const int*   adj_row = (const int*)d_in[1];
    const int*   adj_col = (const int*)d_in[2];
    const float* adj_val = (const float*)d_in[3];

    int n_nodes = in_sizes[0] / LATDIM;
    int n_edges = in_sizes[1];

    float* bufA = nullptr;
    float* bufB = nullptr;
    cudaGetSymbolAddress((void**)&bufA, g_bufA);
    cudaGetSymbolAddress((void**)&bufB, g_bufB);
    float* out = (float*)d_out;

    const int TPB = 256;
    int prep_blocks = (n_nodes * 32 + TPB - 1) / TPB;
    int scan_blocks = (n_nodes + SCAN_B - 1) / SCAN_B;
    int n_warps     = (n_nodes + RPW - 1) / RPW;
    int spmm_blocks = (n_warps * 32 + TPB - 1) / TPB;

    // 1) LN stats + counter zeroing
    prep_kernel<<<prep_blocks, TPB>>>(embeds, n_nodes);
    // 2-5) CSR build
    hist_kernel<<<1024, TPB>>>(adj_row, n_edges);
    scan1_kernel<<<scan_blocks, SCAN_B>>>(n_nodes);
    scan2_kernel<<<1, SCAN_B>>>(scan_blocks);
    scatter_kernel<<<1024, TPB>>>(adj_row, adj_col, adj_val, n_edges);

    // 6) Layer 1: y1 = A * LN(embeds)   (embeds -> bufB, LN fused)
    spmm_kernel<0><<<spmm_blocks, TPB>>>(embeds, bufB, nullptr, nullptr, n_nodes);
    // 7) Layer 2: y2 = A * y1           (bufB -> bufA)
    spmm_kernel<1><<<spmm_blocks, TPB>>>(bufB, bufA, nullptr, nullptr, n_nodes);
    // 8) Layer 3: out = A*y2 + y1 + y2  (gather bufA; add bufB + bufA rows)
    spmm_kernel<2><<<spmm_blocks, TPB>>>(bufA, nullptr, bufB, out, n_nodes);
}

// round 6
// speedup vs baseline: 1.1404x; 1.1404x over previous
#include <cuda_runtime.h>
#include <cuda_bf16.h>

#define NMAX   100000
#define EMAX   640000
#define LATDIM 128
#define VEC    32          // float4 per row
#define SCAN_B 1024
#define RPW    4           // rows per warp in spmm

// ---- scratch (__device__ globals; allocation-free rule) --------------------
__device__ float g_bufA[(size_t)NMAX * LATDIM];
__device__ float g_bufB[(size_t)NMAX * LATDIM];
__device__ int   g_cnt[NMAX];
__device__ int   g_rowstart[NMAX];
__device__ int   g_bsum[SCAN_B];
__device__ int   g_bpref[SCAN_B];
__device__ int   g_rank[EMAX];
__device__ uint2 g_edges[EMAX];     // row-sorted {col, val bits}

// ---------------------------------------------------------------------------
// LayerNorm: warp per node, lane owns one float4; lane0 zeroes g_cnt
// ---------------------------------------------------------------------------
__global__ void ln_kernel(const float* __restrict__ in, float* __restrict__ out,
                          int n_nodes) {
    int gw   = (blockIdx.x * blockDim.x + threadIdx.x) >> 5;
    int lane = threadIdx.x & 31;
    if (gw >= n_nodes) return;

    float4 v = __ldg(reinterpret_cast<const float4*>(in) + (size_t)gw * VEC + lane);

    float s  = v.x + v.y + v.z + v.w;
    float ss = v.x * v.x + v.y * v.y + v.z * v.z + v.w * v.w;
    #pragma unroll
    for (int o = 16; o > 0; o >>= 1) {
        s  += __shfl_xor_sync(0xFFFFFFFFu, s,  o);
        ss += __shfl_xor_sync(0xFFFFFFFFu, ss, o);
    }
    float mu  = s * (1.0f / LATDIM);
    float var = ss * (1.0f / LATDIM) - mu * mu;
    float inv = rsqrtf(var + 1e-5f);

    v.x = (v.x - mu) * inv; v.y = (v.y - mu) * inv;
    v.z = (v.z - mu) * inv; v.w = (v.w - mu) * inv;

    reinterpret_cast<float4*>(out)[(size_t)gw * VEC + lane] = v;
    if (lane == 0) g_cnt[gw] = 0;
}

// ---------------------------------------------------------------------------
// hist: degree count; atomic return value IS the within-row rank
// ---------------------------------------------------------------------------
__global__ void hist_kernel(const int* __restrict__ row, int n_edges) {
    int e      = blockIdx.x * blockDim.x + threadIdx.x;
    int stride = gridDim.x * blockDim.x;
    for (; e < n_edges; e += stride)
        g_rank[e] = atomicAdd(&g_cnt[row[e]], 1);
}

// warp-shuffle block scan (exclusive), emits block total
__global__ void scan1_kernel(int n_nodes) {
    __shared__ int wsum[32];
    int t = threadIdx.x, lane = t & 31, wid = t >> 5;
    int i = blockIdx.x * SCAN_B + t;
    int v = (i < n_nodes) ? g_cnt[i] : 0;

    int x = v;
    #pragma unroll
    for (int o = 1; o < 32; o <<= 1) {
        int y = __shfl_up_sync(0xFFFFFFFFu, x, o);
        if (lane >= o) x += y;
    }
    if (lane == 31) wsum[wid] = x;
    __syncthreads();
    if (wid == 0) {
        int s = wsum[lane];
        #pragma unroll
        for (int o = 1; o < 32; o <<= 1) {
            int y = __shfl_up_sync(0xFFFFFFFFu, s, o);
            if (lane >= o) s += y;
        }
        wsum[lane] = s;
    }
    __syncthreads();
    int incl = x + (wid ? wsum[wid - 1] : 0);
    if (i < n_nodes) g_rowstart[i] = incl - v;
    if (t == SCAN_B - 1) g_bsum[blockIdx.x] = incl;
}

// 128-thread scan of the (<=128) block totals
__global__ void scan2_kernel(int n_blocks) {
    __shared__ int wsum[4];
    int t = threadIdx.x, lane = t & 31, wid = t >> 5;
    int v = (t < n_blocks) ? g_bsum[t] : 0;

    int x = v;
    #pragma unroll
    for (int o = 1; o < 32; o <<= 1) {
        int y = __shfl_up_sync(0xFFFFFFFFu, x, o);
        if (lane >= o) x += y;
    }
    if (lane == 31) wsum[wid] = x;
    __syncthreads();
    int pre = 0;
    #pragma unroll
    for (int w = 0; w < 4; ++w) if (w < wid) pre += wsum[w];
    g_bpref[t] = x + pre - v;
}

// atomic-free scatter using precomputed ranks
__global__ void scatter_kernel(const int* __restrict__ row,
                               const int* __restrict__ col,
                               const float* __restrict__ val,
                               int n_edges) {
    int e      = blockIdx.x * blockDim.x + threadIdx.x;
    int stride = gridDim.x * blockDim.x;
    for (; e < n_edges; e += stride) {
        int r    = row[e];
        int base = g_rowstart[r] + g_bpref[r >> 10];
        g_edges[base + g_rank[e]] =
            make_uint2((unsigned)col[e], __float_as_uint(val[e]));
    }
}

// ---------------------------------------------------------------------------
// SpMM: 4 CSR-adjacent rows per warp. Their edges are CONTIGUOUS in g_edges,
// so one coalesced 32-edge metadata load feeds all 4 rows (~26 of 32 lanes
// useful on average). Inner loops: shuffle broadcast + independent gathers.
// FINAL==0 : y = acc                    (layers 1,2 — zero `out` traffic)
// FINAL==1 : out = acc + y1[r] + x[r]   (layer 3; x row == y2; streaming hints)
// ---------------------------------------------------------------------------
template <int FINAL>
__global__ void __launch_bounds__(256)
spmm_kernel(const float* __restrict__ x,
            float* __restrict__ y,
            const float* __restrict__ y1,
            float* __restrict__ out,
            int n_nodes) {
    int gw = (blockIdx.x * blockDim.x + threadIdx.x) >> 5;
    int r0 = gw * RPW;
    if (r0 >= n_nodes) return;
    int lane = threadIdx.x & 31;

    int base = g_rowstart[r0] + g_bpref[r0 >> 10];   // global start of row r0
    int ofs[RPW + 1];
    ofs[0] = 0;
    #pragma unroll
    for (int j = 0; j < RPW; ++j) {
        int r = r0 + j;
        int d = (r < n_nodes) ? g_cnt[r] : 0;
        ofs[j + 1] = ofs[j] + d;
    }
    int T = ofs[RPW];                                 // total edges of the 4 rows

    const float4* x4 = reinterpret_cast<const float4*>(x);
    float4 acc[RPW];
    #pragma unroll
    for (int j = 0; j < RPW; ++j) acc[j] = make_float4(0.f, 0.f, 0.f, 0.f);

    for (int s = 0; s < T; s += 32) {
        int m = T - s; if (m > 32) m = 32;
        uint2 ev = make_uint2(0u, 0u);
        if (lane < m) ev = __ldg(&g_edges[base + s + lane]);  // one coalesced load

        #pragma unroll
        for (int j = 0; j < RPW; ++j) {
            int k0 = ofs[j]     - s; if (k0 < 0) k0 = 0;
            int k1 = ofs[j + 1] - s; if (k1 > m) k1 = m;
            for (int k = k0; k < k1; ++k) {          // warp-uniform bounds
                int   c = __shfl_sync(0xFFFFFFFFu, (int)ev.x, k);
                float v = __uint_as_float(__shfl_sync(0xFFFFFFFFu, (int)ev.y, k));
                float4 xv = __ldg(x4 + (size_t)c * VEC + lane);
                acc[j].x = fmaf(v, xv.x, acc[j].x);
                acc[j].y = fmaf(v, xv.y, acc[j].y);
                acc[j].z = fmaf(v, xv.z, acc[j].z);
                acc[j].w = fmaf(v, xv.w, acc[j].w);
            }
        }
    }

    #pragma unroll
    for (int j = 0; j < RPW; ++j) {
        int r = r0 + j;
        if (r >= n_nodes) break;
        size_t oi = (size_t)r * VEC + lane;
        if (FINAL == 0) {
            reinterpret_cast<float4*>(y)[oi] = acc[j];   // stays L2-hot
        } else {
            float4 a = __ldcs(reinterpret_cast<const float4*>(y1) + oi); // evict-first
            float4 b = __ldg(x4 + oi);                                   // y2 row: L2-hot
            acc[j].x += a.x + b.x; acc[j].y += a.y + b.y;
            acc[j].z += a.z + b.z; acc[j].w += a.w + b.w;
            __stcs(reinterpret_cast<float4*>(out) + oi, acc[j]);         // streaming
        }
    }
}

// ---------------------------------------------------------------------------
// Launcher
// ---------------------------------------------------------------------------
extern "C" void kernel_launch(void* const* d_in, const int* in_sizes, int n_in,
                              void* d_out, int out_size) {
    const float* embeds  = (const float*)d_in[0];
    const int*   adj_row = (const int*)d_in[1];
    const int*   adj_col = (const int*)d_in[2];
    const float* adj_val = (const float*)d_in[3];

    int n_nodes = in_sizes[0] / LATDIM;
    int n_edges = in_sizes[1];

    float* bufA = nullptr;
    float* bufB = nullptr;
    cudaGetSymbolAddress((void**)&bufA, g_bufA);
    cudaGetSymbolAddress((void**)&bufB, g_bufB);
    float* out = (float*)d_out;

    const int TPB = 256;
    int ln_blocks   = (n_nodes * 32 + TPB - 1) / TPB;
    int scan_blocks = (n_nodes + SCAN_B - 1) / SCAN_B;
    int n_warps     = (n_nodes + RPW - 1) / RPW;
    int spmm_blocks = (n_warps * 32 + TPB - 1) / TPB;

    // 1) LayerNorm (embeds -> bufA) + counter zeroing
    ln_kernel<<<ln_blocks, TPB>>>(embeds, bufA, n_nodes);
    // 2-5) CSR build (rank-based, scatter atomic-free)
    hist_kernel<<<1024, TPB>>>(adj_row, n_edges);
    scan1_kernel<<<scan_blocks, SCAN_B>>>(n_nodes);
    scan2_kernel<<<1, 128>>>(scan_blocks);
    scatter_kernel<<<1024, TPB>>>(adj_row, adj_col, adj_val, n_edges);

    // 6) Layer 1: y1 = A * x0          (bufA -> bufB)
    spmm_kernel<0><<<spmm_blocks, TPB>>>(bufA, bufB, nullptr, nullptr, n_nodes);
    // 7) Layer 2: y2 = A * y1          (bufB -> bufA)
    spmm_kernel<0><<<spmm_blocks, TPB>>>(bufB, bufA, nullptr, nullptr, n_nodes);
    // 8) Layer 3: out = A*y2 + y1 + y2 (gather bufA; add bufB + bufA rows)
    spmm_kernel<1><<<spmm_blocks, TPB>>>(bufA, nullptr, bufB, out, n_nodes);
}